// round 2
// baseline (speedup 1.0000x reference)
#include <cuda_runtime.h>
#include <math.h>

// Problem constants (fixed shapes from reference setup_inputs)
#define BB 2
#define NN 5
#define KSHOT 5
#define QQ 75
#define TT 196
#define CC 384
#define SS (KSHOT*TT)        // 980 shot tokens per class
#define M_TOT (QQ*TT)        // 14700 query-token rows per (b)
#define TEMP_V 10.0f

// Scratch for normalized features (allocation-free: __device__ globals)
__device__ float g_fq[BB*QQ*TT*CC];   // [b][q*t][c] normalized query tokens
__device__ float g_fs[BB*NN*SS*CC];   // [b][n][s][c] normalized shot tokens

// ---------------------------------------------------------------------------
// Warp-per-vector L2 normalization: dst = src / max(||src||, eps)
// which: 0 -> g_fq, 1 -> g_fs
// ---------------------------------------------------------------------------
__global__ void normalize_kernel(const float* __restrict__ src, int nvec,
                                 float eps, int which) {
    int vec = blockIdx.x * 8 + (threadIdx.x >> 5);
    if (vec >= nvec) return;
    float* dstbase = which ? g_fs : g_fq;
    int lane = threadIdx.x & 31;
    const float4* s4 = (const float4*)(src + (size_t)vec * CC);
    float4* d4 = (float4*)(dstbase + (size_t)vec * CC);
    float4 v[3];
    float ss = 0.f;
#pragma unroll
    for (int i = 0; i < 3; i++) {
        v[i] = s4[lane + 32*i];
        ss += v[i].x*v[i].x + v[i].y*v[i].y + v[i].z*v[i].z + v[i].w*v[i].w;
    }
#pragma unroll
    for (int o = 16; o > 0; o >>= 1) ss += __shfl_xor_sync(0xffffffffu, ss, o);
    float inv = 1.0f / fmaxf(sqrtf(ss), eps);
#pragma unroll
    for (int i = 0; i < 3; i++) {
        v[i].x *= inv; v[i].y *= inv; v[i].z *= inv; v[i].w *= inv;
        d4[lane + 32*i] = v[i];
    }
}

__global__ void zero_kernel(float* __restrict__ out, int n) {
    int i = blockIdx.x * 256 + threadIdx.x;
    if (i < n) out[i] = 0.f;
}

// ---------------------------------------------------------------------------
// Main kernel: per (b, n, m-tile) compute sim tile rows vs ALL 980 shot
// tokens, keep running row-max, then atomicAdd max/T into logits[b,q,n].
// Tiles: BM=64 rows x BN=64 cols x BK=16, 256 threads, 4x4 micro-tile.
// ---------------------------------------------------------------------------
#define BM 64
#define BN 64
#define BK 16
#define LDA 68   // padded to break STS bank conflicts, keeps 16B alignment

__global__ __launch_bounds__(256)
void sim_kernel(float* __restrict__ logits) {
    __shared__ float As[BK][LDA];
    __shared__ float Bs[BK][LDA];

    const int mt = blockIdx.x;
    const int n  = blockIdx.y;
    const int b  = blockIdx.z;
    const int m0 = mt * BM;

    const float* Abase = g_fq + (size_t)b * M_TOT * CC;          // [14700][384]
    const float* Bbase = g_fs + ((size_t)b * NN + n) * SS * CC;  // [980][384]

    const int tid  = threadIdx.x;
    const int tx   = tid & 15;        // s micro-tile group
    const int ty   = tid >> 4;        // m micro-tile group
    const int lrow = tid >> 2;        // 0..63 (tile row loaded by this thread)
    const int lk4  = (tid & 3) * 4;   // 0,4,8,12 (k quad)

    float rmax[4] = {-1e30f, -1e30f, -1e30f, -1e30f};

    for (int s0 = 0; s0 < SS; s0 += BN) {
        float acc[4][4] = {};
        for (int k0 = 0; k0 < CC; k0 += BK) {
            // cooperative tile loads (float4, transposed into [k][row])
            {
                int gm = m0 + lrow;
                float4 av = (gm < M_TOT)
                    ? *(const float4*)(Abase + (size_t)gm * CC + k0 + lk4)
                    : make_float4(0.f, 0.f, 0.f, 0.f);
                As[lk4+0][lrow] = av.x;
                As[lk4+1][lrow] = av.y;
                As[lk4+2][lrow] = av.z;
                As[lk4+3][lrow] = av.w;

                int gs = s0 + lrow;
                float4 bv = (gs < SS)
                    ? *(const float4*)(Bbase + (size_t)gs * CC + k0 + lk4)
                    : make_float4(0.f, 0.f, 0.f, 0.f);
                Bs[lk4+0][lrow] = bv.x;
                Bs[lk4+1][lrow] = bv.y;
                Bs[lk4+2][lrow] = bv.z;
                Bs[lk4+3][lrow] = bv.w;
            }
            __syncthreads();
#pragma unroll
            for (int kk = 0; kk < BK; kk++) {
                float4 af = *(const float4*)&As[kk][ty * 4];
                float4 bf = *(const float4*)&Bs[kk][tx * 4];
                float a[4]  = {af.x, af.y, af.z, af.w};
                float bbv[4] = {bf.x, bf.y, bf.z, bf.w};
#pragma unroll
                for (int i = 0; i < 4; i++)
#pragma unroll
                    for (int j = 0; j < 4; j++)
                        acc[i][j] = fmaf(a[i], bbv[j], acc[i][j]);
            }
            __syncthreads();
        }
        // fold this s-tile into running row maxes (mask padded s columns)
#pragma unroll
        for (int j = 0; j < 4; j++) {
            int gs = s0 + tx * 4 + j;
            if (gs < SS) {
#pragma unroll
                for (int i = 0; i < 4; i++)
                    rmax[i] = fmaxf(rmax[i], acc[i][j]);
            }
        }
    }

    // butterfly max-reduce across the 16 tx lanes (each warp = 2 ty halves)
#pragma unroll
    for (int i = 0; i < 4; i++) {
        float v = rmax[i];
#pragma unroll
        for (int o = 8; o > 0; o >>= 1)
            v = fmaxf(v, __shfl_xor_sync(0xffffffffu, v, o));
        rmax[i] = v;
    }

    if (tx == 0) {
#pragma unroll
        for (int i = 0; i < 4; i++) {
            int gm = m0 + ty * 4 + i;
            if (gm < M_TOT) {
                int q = gm / TT;   // query index of this token row
                atomicAdd(&logits[(b * QQ + q) * NN + n],
                          rmax[i] * (1.0f / TT));
            }
        }
    }
}

// ---------------------------------------------------------------------------
// cls branch: one warp per (b,q,n). Fuses proto mean-over-k, both L2 norms
// (eps 1e-12, norms >> eps so x/max(n,eps) == x/n), dot, and temp scale.
// ---------------------------------------------------------------------------
__global__ void cls_kernel(const float* __restrict__ x_shot,
                           const float* __restrict__ x_query,
                           float* __restrict__ cls_out) {
    int w = blockIdx.x * 8 + (threadIdx.x >> 5);
    if (w >= BB * QQ * NN) return;
    int lane = threadIdx.x & 31;
    int n = w % NN;
    int q = (w / NN) % QQ;
    int b = w / (NN * QQ);

    const float* xq = x_query + ((size_t)b * QQ + q) * CC;
    const float* xs = x_shot + ((size_t)b * NN + n) * KSHOT * CC;

    float dot = 0.f, qss = 0.f, pss = 0.f;
#pragma unroll
    for (int i = 0; i < 12; i++) {
        int c = lane + 32 * i;
        float xv = xq[c];
        float pv = 0.f;
#pragma unroll
        for (int kk = 0; kk < KSHOT; kk++) pv += xs[kk * CC + c];
        pv *= (1.0f / KSHOT);
        dot += xv * pv;
        qss += xv * xv;
        pss += pv * pv;
    }
#pragma unroll
    for (int o = 16; o > 0; o >>= 1) {
        dot += __shfl_xor_sync(0xffffffffu, dot, o);
        qss += __shfl_xor_sync(0xffffffffu, qss, o);
        pss += __shfl_xor_sync(0xffffffffu, pss, o);
    }
    if (lane == 0) {
        float v = TEMP_V * dot /
                  (fmaxf(sqrtf(qss), 1e-12f) * fmaxf(sqrtf(pss), 1e-12f));
        cls_out[(b * QQ + q) * NN + n] = v;
    }
}

// ---------------------------------------------------------------------------
extern "C" void kernel_launch(void* const* d_in, const int* in_sizes, int n_in,
                              void* d_out, int out_size) {
    const float* feat_shot  = (const float*)d_in[0];
    const float* feat_query = (const float*)d_in[1];
    const float* x_shot     = (const float*)d_in[2];
    const float* x_query    = (const float*)d_in[3];

    float* out    = (float*)d_out;
    float* logits = out;                 // [b,q,n] = 750
    float* cls    = out + BB * QQ * NN;  // [b,q,n] = 750

    // 1) normalize query / shot token features into scratch
    int nvq = BB * QQ * TT;  // 29400
    int nvs = BB * NN * SS;  // 9800
    normalize_kernel<<<(nvq + 7) / 8, 256>>>(feat_query, nvq, 1e-8f, 0);
    normalize_kernel<<<(nvs + 7) / 8, 256>>>(feat_shot,  nvs, 1e-8f, 1);

    // 2) zero logits (d_out is poisoned), then main sim/max/mean kernel
    zero_kernel<<<(BB * QQ * NN + 255) / 256, 256>>>(logits, BB * QQ * NN);
    dim3 grid((M_TOT + BM - 1) / BM, NN, BB);   // (230, 5, 2)
    sim_kernel<<<grid, 256>>>(logits);

    // 3) tiny cls branch
    int nw = BB * QQ * NN;  // 750 warps
    cls_kernel<<<(nw + 7) / 8, 256>>>(x_shot, x_query, cls);
}

// round 5
// speedup vs baseline: 7.2412x; 7.2412x over previous
#include <cuda_runtime.h>
#include <cuda_bf16.h>
#include <cstdint>
#include <math.h>

// ---------------------------------------------------------------- shapes
#define BB 2
#define NN 5
#define KSHOT 5
#define QQ 75
#define TT 196
#define CC 384
#define SS 980
#define M_REAL (QQ*TT)      // 14700
#define M_PAD  14720        // 115*128, padded rows zero (BSS)
#define S_PAD  1024         // 8*128, padded rows zero (BSS)
#define M_TILES 115
#define S_TILES 8
#define KCH 12              // K chunks of 32 bf16
#define NCHUNK (S_TILES*KCH)  // 96 B chunks
#define TEMP_V 10.0f

// SMEM: A resident: 12 chunks x [128][40] bf16 (80B rows), B: 2-stage ring,
// red: [4][128] floats for cross-warp max reduce.
#define CHUNK_B 10240                 // 128 * 80
#define A_OFF   0
#define B_OFF   (12*CHUNK_B)          // 122880
#define RED_OFF (B_OFF + 2*CHUNK_B)   // 143360
#define SMEM_TOTAL (RED_OFF + 4*128*4)  // 145408

// normalized bf16 scratch, zero-padded (BSS zero-init)
__device__ __nv_bfloat16 g_fq[(size_t)BB*M_PAD*CC];
__device__ __nv_bfloat16 g_fs[(size_t)BB*NN*S_PAD*CC];

// ---------------------------------------------------------------- helpers
__device__ __forceinline__ uint32_t smem_u32(const void* p) {
    uint32_t a;
    asm("{ .reg .u64 t; cvta.to.shared.u64 t, %1; cvt.u32.u64 %0, t; }"
        : "=r"(a) : "l"(p));
    return a;
}
#define CP_ASYNC16(dst, gsrc) \
    asm volatile("cp.async.cg.shared.global [%0], [%1], 16;" :: "r"(dst), "l"(gsrc) : "memory")
#define CP_COMMIT() asm volatile("cp.async.commit_group;" ::: "memory")
#define CP_WAIT0()  asm volatile("cp.async.wait_group 0;" ::: "memory")

__device__ __forceinline__ void ldsm4(uint32_t (&r)[4], uint32_t addr) {
    asm volatile("ldmatrix.sync.aligned.m8n8.x4.shared.b16 {%0,%1,%2,%3}, [%4];"
        : "=r"(r[0]), "=r"(r[1]), "=r"(r[2]), "=r"(r[3]) : "r"(addr));
}
__device__ __forceinline__ void mma16816(float (&d)[4], const uint32_t (&a)[4],
                                         uint32_t b0, uint32_t b1) {
    asm volatile("mma.sync.aligned.m16n8k16.row.col.f32.bf16.bf16.f32 "
        "{%0,%1,%2,%3}, {%4,%5,%6,%7}, {%8,%9}, {%0,%1,%2,%3};"
        : "+f"(d[0]), "+f"(d[1]), "+f"(d[2]), "+f"(d[3])
        : "r"(a[0]), "r"(a[1]), "r"(a[2]), "r"(a[3]), "r"(b0), "r"(b1));
}

// ---------------------------------------------------------------- normalize
__global__ void normalize_fq(const float* __restrict__ src) {
    int vec = blockIdx.x * 8 + (threadIdx.x >> 5);
    if (vec >= BB * M_REAL) return;
    int lane = threadIdx.x & 31;
    int b = vec / M_REAL, m = vec - b * M_REAL;
    const float2* s2 = (const float2*)(src + (size_t)vec * CC);
    __nv_bfloat162* d2 = (__nv_bfloat162*)(g_fq + ((size_t)b * M_PAD + m) * CC);
    float2 v[6]; float ss = 0.f;
#pragma unroll
    for (int i = 0; i < 6; i++) { v[i] = s2[lane + 32*i]; ss += v[i].x*v[i].x + v[i].y*v[i].y; }
#pragma unroll
    for (int o = 16; o > 0; o >>= 1) ss += __shfl_xor_sync(0xffffffffu, ss, o);
    float inv = 1.0f / fmaxf(sqrtf(ss), 1e-8f);
#pragma unroll
    for (int i = 0; i < 6; i++)
        d2[lane + 32*i] = __floats2bfloat162_rn(v[i].x * inv, v[i].y * inv);
}

__global__ void normalize_fs(const float* __restrict__ src) {
    int vec = blockIdx.x * 8 + (threadIdx.x >> 5);
    if (vec >= BB * NN * SS) return;
    int lane = threadIdx.x & 31;
    int b = vec / (NN * SS); int rem = vec - b * NN * SS;
    int n = rem / SS, s = rem - n * SS;
    const float2* s2 = (const float2*)(src + (size_t)vec * CC);
    __nv_bfloat162* d2 = (__nv_bfloat162*)(g_fs + (((size_t)(b * NN + n)) * S_PAD + s) * CC);
    float2 v[6]; float ss = 0.f;
#pragma unroll
    for (int i = 0; i < 6; i++) { v[i] = s2[lane + 32*i]; ss += v[i].x*v[i].x + v[i].y*v[i].y; }
#pragma unroll
    for (int o = 16; o > 0; o >>= 1) ss += __shfl_xor_sync(0xffffffffu, ss, o);
    float inv = 1.0f / fmaxf(sqrtf(ss), 1e-8f);
#pragma unroll
    for (int i = 0; i < 6; i++)
        d2[lane + 32*i] = __floats2bfloat162_rn(v[i].x * inv, v[i].y * inv);
}

__global__ void zero_kernel(float* __restrict__ out, int n) {
    int i = blockIdx.x * 256 + threadIdx.x;
    if (i < n) out[i] = 0.f;
}

// ---------------------------------------------------------------- sim (HMMA)
// CTA: 128 query rows x one (b,n). A resident in SMEM (12 k-chunks),
// B streamed in 96 chunks of [128 rows][32 k] through a 2-stage cp.async ring.
// 8 warps: warp_m = wid&1 (64 rows), warp_n = wid>>1 (32 cols).
__global__ __launch_bounds__(256)
void sim_kernel(float* __restrict__ logits) {
    extern __shared__ char smem[];
    const uint32_t sb = smem_u32(smem);
    float* red = (float*)(smem + RED_OFF);

    const int tid = threadIdx.x, lane = tid & 31, wid = tid >> 5;
    const int warp_m = wid & 1, warp_n = wid >> 1;
    const int mt = blockIdx.x, n = blockIdx.y, b = blockIdx.z;
    const int m0 = mt * 128;

    // per-thread cp.async mapping: row = tid/2, two 16B segs
    const int ld_row = tid >> 1;
    const int seg0 = (tid & 1) * 2;

    // ---- preload resident A (one commit group) ----
    {
        const __nv_bfloat16* Ab = g_fq + ((size_t)b * M_PAD + m0) * CC;
#pragma unroll
        for (int kc = 0; kc < KCH; kc++) {
            const __nv_bfloat16* srow = Ab + (size_t)ld_row * CC + kc * 32;
            uint32_t drow = sb + A_OFF + kc * CHUNK_B + ld_row * 80;
#pragma unroll
            for (int s = 0; s < 2; s++) {
                int sc = seg0 + s;
                CP_ASYNC16(drow + sc * 16, __cvta_generic_to_global(srow + sc * 8));
            }
        }
        CP_COMMIT();
    }
    const __nv_bfloat16* Bb = g_fs + ((size_t)(b * NN + n)) * S_PAD * CC;
    auto issueB = [&](int j) {
        int st = j / KCH, kc = j - st * KCH;
        const __nv_bfloat16* srow = Bb + ((size_t)(st * 128 + ld_row)) * CC + kc * 32;
        uint32_t drow = sb + B_OFF + (j & 1) * CHUNK_B + ld_row * 80;
#pragma unroll
        for (int s = 0; s < 2; s++) {
            int sc = seg0 + s;
            CP_ASYNC16(drow + sc * 16, __cvta_generic_to_global(srow + sc * 8));
        }
        CP_COMMIT();
    };
    issueB(0);
    CP_WAIT0();            // A + B0 landed
    __syncthreads();

    // ldmatrix lane offsets (80B row stride)
    const uint32_t a_base = (uint32_t)(warp_m * 64 + (lane & 15)) * 80 + (lane >> 4) * 16;
    const uint32_t b_base = (uint32_t)(warp_n * 32 + ((lane >> 4) << 3) + (lane & 7)) * 80
                          + ((lane >> 3) & 1) * 16;

    float rmax[4][2];
#pragma unroll
    for (int mf = 0; mf < 4; mf++) { rmax[mf][0] = -1e30f; rmax[mf][1] = -1e30f; }

    float acc[4][4][4];

    for (int j = 0; j < NCHUNK; j++) {
        const int st = j / KCH, kc = j - st * KCH;
        if (kc == 0) {
#pragma unroll
            for (int mf = 0; mf < 4; mf++)
#pragma unroll
                for (int nf = 0; nf < 4; nf++)
#pragma unroll
                    for (int c = 0; c < 4; c++) acc[mf][nf][c] = 0.f;
        }
        if (j + 1 < NCHUNK) issueB(j + 1);   // other stage, safe: sync'd last iter

        const uint32_t Ach = sb + A_OFF + kc * CHUNK_B;
        const uint32_t Bch = sb + B_OFF + (j & 1) * CHUNK_B;
#pragma unroll
        for (int ks = 0; ks < 2; ks++) {
            uint32_t a[4][4];
#pragma unroll
            for (int mf = 0; mf < 4; mf++)
                ldsm4(a[mf], Ach + a_base + mf * (16 * 80) + ks * 32);
            uint32_t bf[2][4];
#pragma unroll
            for (int p = 0; p < 2; p++)
                ldsm4(bf[p], Bch + b_base + p * (16 * 80) + ks * 32);
#pragma unroll
            for (int mf = 0; mf < 4; mf++)
#pragma unroll
                for (int p = 0; p < 2; p++) {
                    mma16816(acc[mf][p*2+0], a[mf], bf[p][0], bf[p][1]);
                    mma16816(acc[mf][p*2+1], a[mf], bf[p][2], bf[p][3]);
                }
        }

        if (kc == KCH - 1) {
            const int s0 = st * 128;
#pragma unroll
            for (int mf = 0; mf < 4; mf++)
#pragma unroll
                for (int nf = 0; nf < 4; nf++) {
                    int colb = s0 + warp_n * 32 + nf * 8 + (lane & 3) * 2;
                    const float* c = acc[mf][nf];
                    if (colb < SS) {
                        rmax[mf][0] = fmaxf(rmax[mf][0], c[0]);
                        rmax[mf][1] = fmaxf(rmax[mf][1], c[2]);
                    }
                    if (colb + 1 < SS) {
                        rmax[mf][0] = fmaxf(rmax[mf][0], c[1]);
                        rmax[mf][1] = fmaxf(rmax[mf][1], c[3]);
                    }
                }
        }

        if (j + 1 < NCHUNK) CP_WAIT0();
        __syncthreads();
    }

    // lane reduce (lanes xor 1, 2 share rows), write red[warp_n][row]
#pragma unroll
    for (int mf = 0; mf < 4; mf++)
#pragma unroll
        for (int r2 = 0; r2 < 2; r2++) {
            float v = rmax[mf][r2];
            v = fmaxf(v, __shfl_xor_sync(0xffffffffu, v, 1));
            v = fmaxf(v, __shfl_xor_sync(0xffffffffu, v, 2));
            if ((lane & 3) == 0) {
                int row = warp_m * 64 + mf * 16 + (lane >> 2) + r2 * 8;
                red[warp_n * 128 + row] = v;
            }
        }
    __syncthreads();

    if (tid < 128) {
        float v = fmaxf(fmaxf(red[tid], red[128 + tid]),
                        fmaxf(red[256 + tid], red[384 + tid]));
        int row = m0 + tid;
        if (row < M_REAL) {
            int q = row / TT;
            atomicAdd(logits + ((size_t)b * QQ + q) * NN + n, v * (1.0f / TT));
        }
    }
}

// ---------------------------------------------------------------- cls branch
__global__ void cls_kernel(const float* __restrict__ x_shot,
                           const float* __restrict__ x_query,
                           float* __restrict__ cls_out) {
    int w = blockIdx.x * 8 + (threadIdx.x >> 5);
    if (w >= BB * QQ * NN) return;
    int lane = threadIdx.x & 31;
    int n = w % NN;
    int q = (w / NN) % QQ;
    int b = w / (NN * QQ);
    const float* xq = x_query + ((size_t)b * QQ + q) * CC;
    const float* xs = x_shot + ((size_t)b * NN + n) * KSHOT * CC;
    float dot = 0.f, qss = 0.f, pss = 0.f;
#pragma unroll
    for (int i = 0; i < 12; i++) {
        int c = lane + 32 * i;
        float xv = xq[c];
        float pv = 0.f;
#pragma unroll
        for (int kk = 0; kk < KSHOT; kk++) pv += xs[kk * CC + c];
        pv *= (1.0f / KSHOT);
        dot += xv * pv; qss += xv * xv; pss += pv * pv;
    }
#pragma unroll
    for (int o = 16; o > 0; o >>= 1) {
        dot += __shfl_xor_sync(0xffffffffu, dot, o);
        qss += __shfl_xor_sync(0xffffffffu, qss, o);
        pss += __shfl_xor_sync(0xffffffffu, pss, o);
    }
    if (lane == 0) {
        cls_out[(b * QQ + q) * NN + n] = TEMP_V * dot /
            (fmaxf(sqrtf(qss), 1e-12f) * fmaxf(sqrtf(pss), 1e-12f));
    }
}

// ----------------------------------------------------------------
extern "C" void kernel_launch(void* const* d_in, const int* in_sizes, int n_in,
                              void* d_out, int out_size) {
    const float* feat_shot  = (const float*)d_in[0];
    const float* feat_query = (const float*)d_in[1];
    const float* x_shot     = (const float*)d_in[2];
    const float* x_query    = (const float*)d_in[3];

    float* out    = (float*)d_out;
    float* logits = out;                 // [b,q,n] = 750
    float* cls    = out + BB * QQ * NN;  // [b,q,n] = 750

    int nvq = BB * M_REAL;        // 29400
    int nvs = BB * NN * SS;       // 9800
    normalize_fq<<<(nvq + 7) / 8, 256>>>(feat_query);
    normalize_fs<<<(nvs + 7) / 8, 256>>>(feat_shot);

    zero_kernel<<<(BB * QQ * NN + 255) / 256, 256>>>(logits, BB * QQ * NN);

    static bool attr_done = false;
    if (!attr_done) {
        cudaFuncSetAttribute(sim_kernel,
                             cudaFuncAttributeMaxDynamicSharedMemorySize, SMEM_TOTAL);
        attr_done = true;
    }
    dim3 grid(M_TILES, NN, BB);   // (115, 5, 2)
    sim_kernel<<<grid, 256, SMEM_TOTAL>>>(logits);

    int nw = BB * QQ * NN;        // 750 warps
    cls_kernel<<<(nw + 7) / 8, 256>>>(x_shot, x_query, cls);
}